// round 2
// baseline (speedup 1.0000x reference)
#include <cuda_runtime.h>
#include <math.h>
#include <float.h>

#define BATCH 64
#define NQ 900
#define NT 128
#define NC 14   // NUM_CLASSES + 1

// Scratch (no allocations allowed) — cost stored transposed: [b][t][q]
__device__ float  g_cost[BATCH * NT * NQ];
__device__ int    g_match[BATCH * NT];      // query assigned to target t
__device__ double g_partial[BATCH];

// ---------------------------------------------------------------------------
// Kernel 1: cost matrix  C[b][t][q] = L1(bbox) - softmax(logits)[label]
// ---------------------------------------------------------------------------
__global__ void __launch_bounds__(256) cost_kernel(const float* __restrict__ pc,
                                                   const float* __restrict__ pb,
                                                   const int*   __restrict__ tl,
                                                   const float* __restrict__ tb) {
    int b = blockIdx.x, tid = threadIdx.x;
    __shared__ int    s_lab[NT];
    __shared__ float4 s_tb[NT];
    __shared__ float  s_prob[NC][256];   // per-thread softmax probs (dynamic index -> shared)

    if (tid < NT) {
        s_lab[tid] = tl[b * NT + tid];
        s_tb[tid]  = reinterpret_cast<const float4*>(tb)[b * NT + tid];
    }
    __syncthreads();

    for (int q0 = 0; q0 < NQ; q0 += 256) {
        int q = q0 + tid;
        if (q < NQ) {
            const float* lg = pc + ((size_t)b * NQ + q) * NC;
            float lgl[NC];
            float m = -FLT_MAX;
            #pragma unroll
            for (int k = 0; k < NC; k++) { lgl[k] = lg[k]; m = fmaxf(m, lgl[k]); }
            float s = 0.f;
            #pragma unroll
            for (int k = 0; k < NC; k++) { float e = expf(lgl[k] - m); s_prob[k][tid] = e; s += e; }
            float inv = 1.0f / s;
            #pragma unroll
            for (int k = 0; k < NC; k++) s_prob[k][tid] *= inv;

            float4 p4 = reinterpret_cast<const float4*>(pb)[b * NQ + q];
            float* base = g_cost + (size_t)b * NT * NQ + q;
            #pragma unroll 4
            for (int t = 0; t < NT; t++) {
                float4 t4 = s_tb[t];
                float cb = fabsf(p4.x - t4.x) + fabsf(p4.y - t4.y) +
                           fabsf(p4.z - t4.z) + fabsf(p4.w - t4.w);
                base[(size_t)t * NQ] = cb - s_prob[s_lab[t]][tid];
            }
        }
    }
}

// ---------------------------------------------------------------------------
// Kernel 2: exact JV Hungarian per image (double-precision duals, matching the
// float64 reference). n = NT targets (rows), m = NQ queries (cols).
// One block per image; inner O(m) scans parallelized over 256 threads.
// ---------------------------------------------------------------------------
#define INF_D 1e300

__global__ void __launch_bounds__(256) hungarian_kernel() {
    const int b = blockIdx.x;
    const int tid = threadIdx.x;
    const float* C = g_cost + (size_t)b * NT * NQ;   // [t][q]

    __shared__ double u[NT + 1];
    __shared__ double v[NQ + 1];
    __shared__ double minv[NQ + 1];
    __shared__ int    way[NQ + 1];
    __shared__ int    p[NQ + 1];
    __shared__ unsigned char used[NQ + 1];
    __shared__ double s_wval[8];
    __shared__ int    s_widx[8];
    __shared__ double s_delta;
    __shared__ int    s_j0, s_j1;

    for (int j = tid; j <= NQ; j += 256) { v[j] = 0.0; p[j] = 0; way[j] = 0; }
    for (int i = tid; i <= NT; i += 256) u[i] = 0.0;
    __syncthreads();

    for (int i = 1; i <= NT; i++) {
        for (int j = tid; j <= NQ; j += 256) { minv[j] = INF_D; used[j] = 0; }
        if (tid == 0) { p[0] = i; s_j0 = 0; }
        __syncthreads();

        while (true) {
            int j0 = s_j0;
            if (tid == 0) used[j0] = 1;
            __syncthreads();

            int i0 = p[j0];
            double ui0 = u[i0];
            const float* crow = C + (size_t)(i0 - 1) * NQ;

            // scan pass: update minv/way, track local (min, argmin) over free cols
            double bestv = INF_D; int besti = 0x7fffffff;
            for (int j = 1 + tid; j <= NQ; j += 256) {
                if (!used[j]) {
                    double cur = (double)crow[j - 1] - ui0 - v[j];
                    double mv = minv[j];
                    if (cur < mv) { mv = cur; minv[j] = cur; way[j] = j0; }
                    if (mv < bestv) { bestv = mv; besti = j; }
                }
            }
            // warp argmin reduce (tie -> smaller index, matches np.argmin)
            #pragma unroll
            for (int off = 16; off > 0; off >>= 1) {
                double ov = __shfl_down_sync(0xffffffffu, bestv, off);
                int    oi = __shfl_down_sync(0xffffffffu, besti, off);
                if (ov < bestv || (ov == bestv && oi < besti)) { bestv = ov; besti = oi; }
            }
            int wid = tid >> 5;
            if ((tid & 31) == 0) { s_wval[wid] = bestv; s_widx[wid] = besti; }
            __syncthreads();
            if (tid == 0) {
                double bv = s_wval[0]; int bi = s_widx[0];
                #pragma unroll
                for (int w = 1; w < 8; w++) {
                    double ov = s_wval[w]; int oi = s_widx[w];
                    if (ov < bv || (ov == bv && oi < bi)) { bv = ov; bi = oi; }
                }
                s_delta = bv; s_j1 = bi;
            }
            __syncthreads();

            double delta = s_delta;
            int j1 = s_j1;

            // dual update pass
            for (int j = tid; j <= NQ; j += 256) {
                if (used[j]) { u[p[j]] += delta; v[j] -= delta; }
                else if (j >= 1) minv[j] -= delta;
            }
            __syncthreads();

            bool done = (p[j1] == 0);
            if (tid == 0) s_j0 = j1;
            __syncthreads();
            if (done) break;
        }

        // augment along way[] (serial, tiny)
        if (tid == 0) {
            int j0 = s_j0;
            while (j0 != 0) { int j1 = way[j0]; p[j0] = p[j1]; j0 = j1; }
        }
        __syncthreads();
    }

    for (int j = 1 + tid; j <= NQ; j += 256) {
        int pi = p[j];
        if (pi > 0) g_match[b * NT + (pi - 1)] = j - 1;
    }
}

// ---------------------------------------------------------------------------
// Kernel 3: per-image loss (bbox L1 + GIoU + weighted CE over 900 queries)
// ---------------------------------------------------------------------------
__device__ __forceinline__ double block_reduce(double val, double* red, int tid) {
    red[tid] = val;
    __syncthreads();
    for (int s = 128; s > 0; s >>= 1) {
        if (tid < s) red[tid] += red[tid + s];
        __syncthreads();
    }
    double r = red[0];
    __syncthreads();
    return r;
}

__global__ void __launch_bounds__(256) loss_kernel(const float* __restrict__ pc,
                                                   const float* __restrict__ pb,
                                                   const int*   __restrict__ tl,
                                                   const float* __restrict__ tb) {
    int b = blockIdx.x, tid = threadIdx.x;
    __shared__ int cls[NQ];
    __shared__ double red[256];

    for (int q = tid; q < NQ; q += 256) cls[q] = NC - 1;   // "no object" class 13
    __syncthreads();

    double l1sum = 0.0, gsum = 0.0;
    if (tid < NT) {
        int t = tid;
        int q = g_match[b * NT + t];
        int lab = tl[b * NT + t];
        cls[q] = lab;

        float4 p4 = reinterpret_cast<const float4*>(pb)[b * NQ + q];
        float4 t4 = reinterpret_cast<const float4*>(tb)[b * NT + t];
        l1sum = (double)(fabsf(p4.x - t4.x) + fabsf(p4.y - t4.y) +
                         fabsf(p4.z - t4.z) + fabsf(p4.w - t4.w));

        // cxcywh -> xyxy
        float px0 = p4.x - 0.5f * p4.z, py0 = p4.y - 0.5f * p4.w;
        float px1 = p4.x + 0.5f * p4.z, py1 = p4.y + 0.5f * p4.w;
        float tx0 = t4.x - 0.5f * t4.z, ty0 = t4.y - 0.5f * t4.w;
        float tx1 = t4.x + 0.5f * t4.z, ty1 = t4.y + 0.5f * t4.w;
        float a1 = (px1 - px0) * (py1 - py0);
        float a2 = (tx1 - tx0) * (ty1 - ty0);
        float ltx = fmaxf(px0, tx0), lty = fmaxf(py0, ty0);
        float rbx = fminf(px1, tx1), rby = fminf(py1, ty1);
        float iw = fmaxf(rbx - ltx, 0.f), ih = fmaxf(rby - lty, 0.f);
        float inter = iw * ih;
        float uni = a1 + a2 - inter;
        float iou = inter / uni;
        float cx0 = fminf(px0, tx0), cy0 = fminf(py0, ty0);
        float cx1 = fmaxf(px1, tx1), cy1 = fmaxf(py1, ty1);
        float cw = fmaxf(cx1 - cx0, 0.f), ch = fmaxf(cy1 - cy0, 0.f);
        float ac = cw * ch;
        float giou = iou - (ac - uni) / ac;
        gsum = (double)(1.0f - giou);
    }
    __syncthreads();  // cls writes visible

    double wnll = 0.0, wsum = 0.0;
    for (int q = tid; q < NQ; q += 256) {
        const float* lg = pc + ((size_t)b * NQ + q) * NC;
        float lgl[NC];
        float m = -FLT_MAX;
        #pragma unroll
        for (int k = 0; k < NC; k++) { lgl[k] = lg[k]; m = fmaxf(m, lgl[k]); }
        float s = 0.f;
        #pragma unroll
        for (int k = 0; k < NC; k++) s += expf(lgl[k] - m);
        float lse = logf(s) + m;
        int c = cls[q];
        float nll = lse - lgl[c];
        float w = (c == NC - 1) ? 0.05f : 1.0f;
        wnll += (double)(w * nll);
        wsum += (double)w;
    }

    double L1 = block_reduce(l1sum, red, tid);
    double G  = block_reduce(gsum, red, tid);
    double WN = block_reduce(wnll, red, tid);
    double WS = block_reduce(wsum, red, tid);

    if (tid == 0) {
        double l1_mean = L1 / (double)(NT * 4);
        double bbox = 5.0 * l1_mean + 2.0 * (G / (double)NT);
        g_partial[b] = WN / WS + bbox;
    }
}

__global__ void finalize_kernel(float* out) {
    __shared__ double red[64];
    int tid = threadIdx.x;
    red[tid] = g_partial[tid];
    __syncthreads();
    for (int s = 32; s > 0; s >>= 1) {
        if (tid < s) red[tid] += red[tid + s];
        __syncthreads();
    }
    if (tid == 0) out[0] = (float)(red[0] / (double)(BATCH * NT));
}

// ---------------------------------------------------------------------------
extern "C" void kernel_launch(void* const* d_in, const int* in_sizes, int n_in,
                              void* d_out, int out_size) {
    const float* pc = (const float*)d_in[0];  // [64,900,14]
    const float* pb = (const float*)d_in[1];  // [64,900,4]
    const int*   tl = (const int*)d_in[2];    // [64,128]
    const float* tb = (const float*)d_in[3];  // [64,128,4]

    cost_kernel<<<BATCH, 256>>>(pc, pb, tl, tb);
    hungarian_kernel<<<BATCH, 256>>>();
    loss_kernel<<<BATCH, 256>>>(pc, pb, tl, tb);
    finalize_kernel<<<1, 64>>>((float*)d_out);
}

// round 3
// speedup vs baseline: 5.7477x; 5.7477x over previous
#include <cuda_runtime.h>
#include <math.h>
#include <float.h>

#define BATCH 64
#define NQ 900
#define NT 128
#define NC 14     // NUM_CLASSES + 1
#define CAP 160   // max candidates kept per row (top-128 superset)
#define NBINS 512

// ---- global scratch (no allocations allowed) ----
__device__ float          g_cost[BATCH * NT * NQ];        // [b][t][q]
__device__ float          g_candcost[BATCH * NT * CAP];
__device__ unsigned short g_candcol[BATCH * NT * CAP];
__device__ int            g_candcnt[BATCH * NT];
__device__ float          g_rowmin[BATCH * NT];
__device__ int            g_rowargmin[BATCH * NT];
__device__ int            g_match[BATCH * NT];            // query assigned to target t
__device__ double         g_partial[BATCH];

// ---------------------------------------------------------------------------
// Kernel 1: cost matrix  C[b][t][q] = L1(bbox) - softmax(logits)[label]
// ---------------------------------------------------------------------------
__global__ void __launch_bounds__(256) cost_kernel(const float* __restrict__ pc,
                                                   const float* __restrict__ pb,
                                                   const int*   __restrict__ tl,
                                                   const float* __restrict__ tb) {
    int b = blockIdx.x, tid = threadIdx.x;
    __shared__ int    s_lab[NT];
    __shared__ float4 s_tb[NT];
    __shared__ float  s_prob[NC][256];

    if (tid < NT) {
        s_lab[tid] = tl[b * NT + tid];
        s_tb[tid]  = reinterpret_cast<const float4*>(tb)[b * NT + tid];
    }
    __syncthreads();

    for (int q0 = 0; q0 < NQ; q0 += 256) {
        int q = q0 + tid;
        if (q < NQ) {
            const float* lg = pc + ((size_t)b * NQ + q) * NC;
            float lgl[NC];
            float m = -FLT_MAX;
            #pragma unroll
            for (int k = 0; k < NC; k++) { lgl[k] = lg[k]; m = fmaxf(m, lgl[k]); }
            float s = 0.f;
            #pragma unroll
            for (int k = 0; k < NC; k++) { float e = expf(lgl[k] - m); s_prob[k][tid] = e; s += e; }
            float inv = 1.0f / s;
            #pragma unroll
            for (int k = 0; k < NC; k++) s_prob[k][tid] *= inv;

            float4 p4 = reinterpret_cast<const float4*>(pb)[b * NQ + q];
            float* base = g_cost + (size_t)b * NT * NQ + q;
            #pragma unroll 4
            for (int t = 0; t < NT; t++) {
                float4 t4 = s_tb[t];
                float cb = fabsf(p4.x - t4.x) + fabsf(p4.y - t4.y) +
                           fabsf(p4.z - t4.z) + fabsf(p4.w - t4.w);
                base[(size_t)t * NQ] = cb - s_prob[s_lab[t]][tid];
            }
        }
    }
}

// ---------------------------------------------------------------------------
// Kernel 2: per-row candidate selection. Keeps all entries below a histogram
// threshold guaranteed to cover the row's 128 smallest. Also row min/argmin.
// ---------------------------------------------------------------------------
__global__ void __launch_bounds__(128) select_kernel() {
    int row = blockIdx.x;   // b*NT + t
    int tid = threadIdx.x;
    const float* C = g_cost + (size_t)row * NQ;

    __shared__ int   hist[NBINS];
    __shared__ float red_v[128];
    __shared__ int   red_i[128];
    __shared__ float red_mx[128];
    __shared__ int   wsum[4];
    __shared__ float s_min, s_max, s_tau;
    __shared__ int   s_argmin, s_cnt;

    float c[8];
    float lmin = FLT_MAX, lmax = -FLT_MAX; int larg = 0;
    #pragma unroll
    for (int k = 0; k < 8; k++) {
        int j = tid + 128 * k;
        float v = (j < NQ) ? C[j] : FLT_MAX;
        c[k] = v;
        if (v < lmin) { lmin = v; larg = j; }
        if (j < NQ && v > lmax) lmax = v;
    }
    red_v[tid] = lmin; red_i[tid] = larg; red_mx[tid] = lmax;
    __syncthreads();
    for (int s = 64; s > 0; s >>= 1) {
        if (tid < s) {
            if (red_v[tid + s] < red_v[tid]) { red_v[tid] = red_v[tid + s]; red_i[tid] = red_i[tid + s]; }
            if (red_mx[tid + s] > red_mx[tid]) red_mx[tid] = red_mx[tid + s];
        }
        __syncthreads();
    }
    if (tid == 0) { s_min = red_v[0]; s_argmin = red_i[0]; s_max = red_mx[0]; s_cnt = 0; }
    for (int h = tid; h < NBINS; h += 128) hist[h] = 0;
    __syncthreads();

    float mn = s_min;
    float scale = (float)NBINS / fmaxf(s_max - mn, 1e-30f) * 0.999999f;
    #pragma unroll
    for (int k = 0; k < 8; k++) {
        int j = tid + 128 * k;
        if (j < NQ) {
            int bb = (int)((c[k] - mn) * scale);
            bb = min(max(bb, 0), NBINS - 1);
            atomicAdd(&hist[bb], 1);
        }
    }
    __syncthreads();

    // inclusive scan over 128 per-thread partials (4 bins each)
    int part = hist[4 * tid] + hist[4 * tid + 1] + hist[4 * tid + 2] + hist[4 * tid + 3];
    int lane = tid & 31, wid = tid >> 5;
    int x = part;
    #pragma unroll
    for (int off = 1; off < 32; off <<= 1) {
        int y = __shfl_up_sync(0xffffffffu, x, off);
        if (lane >= off) x += y;
    }
    if (lane == 31) wsum[wid] = x;
    __syncthreads();
    int add = 0;
    for (int w = 0; w < wid; w++) add += wsum[w];
    int inc = x + add;
    int exc = inc - part;
    if (inc >= NT && exc < NT) {      // exactly one thread crosses 128
        int running = exc, tbin = 4 * tid;
        #pragma unroll
        for (int q = 0; q < 4; q++) {
            running += hist[4 * tid + q];
            if (running >= NT) { tbin = 4 * tid + q; break; }
        }
        s_tau = mn + ((float)tbin + 1.5f) / scale;  // +half bin: safe superset margin
    }
    __syncthreads();

    float tau = s_tau;
    int base = row * CAP;
    #pragma unroll
    for (int k = 0; k < 8; k++) {
        int j = tid + 128 * k;
        if (j < NQ && c[k] < tau) {
            int slot = atomicAdd(&s_cnt, 1);
            if (slot < CAP) {
                g_candcost[base + slot] = c[k];
                g_candcol[base + slot] = (unsigned short)j;
            }
        }
    }
    __syncthreads();
    if (tid == 0) {
        g_candcnt[row]   = min(s_cnt, CAP);
        g_rowmin[row]    = s_min;
        g_rowargmin[row] = s_argmin;
    }
}

// ---------------------------------------------------------------------------
// Kernel 3: exact sparse SSP Hungarian per image (scipy-style), duals double.
// Candidates cached in shared memory; dist keys packed u64 for cheap argmin.
// ---------------------------------------------------------------------------
#define KMAX 0xFFFFFFFFFFFFFFFFull

extern __shared__ char hsm[];

__global__ void __launch_bounds__(128) hungarian_kernel() {
    const int b = blockIdx.x, tid = threadIdx.x;

    // shared layout (8B-aligned first)
    double*             v       = (double*)hsm;                               // 900
    unsigned long long* dist    = (unsigned long long*)(v + NQ);              // 900
    double*             scval   = (double*)(dist + NQ);                       // 900
    double*             u       = scval + NQ;                                 // 128
    float*              ccost   = (float*)(u + NT);                           // 128*CAP
    unsigned short*     ccol    = (unsigned short*)(ccost + NT * CAP);        // 128*CAP
    short*              row4col = (short*)(ccol + NT * CAP);                  // 900
    short*              col4row = row4col + NQ;                               // 128
    unsigned short*     sccol   = (unsigned short*)(col4row + NT);            // 900
    short*              cnt_s   = (short*)(sccol + NQ);                       // 128
    unsigned char*      path    = (unsigned char*)(cnt_s + NT);               // 900
    unsigned char*      scflag  = path + NQ;                                  // 900

    __shared__ unsigned long long s_best;
    __shared__ double s_minval, s_fm;
    __shared__ int s_i, s_len, s_done, s_sink;

    // ---- init ----
    for (int idx = tid; idx < NT * CAP; idx += 128) {
        ccost[idx] = g_candcost[b * NT * CAP + idx];
        ccol[idx]  = g_candcol[b * NT * CAP + idx];
    }
    if (tid < NT) {
        cnt_s[tid]   = (short)g_candcnt[b * NT + tid];
        u[tid]       = (double)g_rowmin[b * NT + tid];
        col4row[tid] = -1;
    }
    for (int j = tid; j < NQ; j += 128) {
        v[j] = 0.0; row4col[j] = -1; scflag[j] = 0; dist[j] = KMAX;
    }
    if (tid == 0) s_best = KMAX;
    __syncthreads();

    // greedy warm start: row argmin is dual-tight (u[i] = rowmin, v = 0)
    if (tid == 0) {
        for (int r = 0; r < NT; r++) {
            int j = g_rowargmin[b * NT + r];
            if (row4col[j] < 0) { row4col[j] = (short)r; col4row[r] = (short)j; }
        }
    }
    __syncthreads();

    for (int curRow = 0; curRow < NT; curRow++) {
        if (col4row[curRow] >= 0) continue;

        for (int j = tid; j < NQ; j += 128) dist[j] = KMAX;
        if (tid == 0) { s_i = curRow; s_minval = 0.0; s_len = 0; s_done = 0; }
        __syncthreads();

        while (true) {
            int i = s_i;
            double minv = s_minval;
            double ui = u[i];
            int cn = cnt_s[i];
            const float* rc          = ccost + i * CAP;
            const unsigned short* rl = ccol  + i * CAP;

            unsigned long long local = KMAX;
            // fused relax(new row's candidates) + contribute new keys to argmin
            for (int cc = tid; cc < cn; cc += 128) {
                int col = rl[cc];
                if (!scflag[col]) {
                    double r = minv + (double)rc[cc] - ui - v[col];
                    r = fmax(r, 0.0);
                    unsigned long long key =
                        (((unsigned long long)__double_as_longlong(r)) & ~1023ull) | (unsigned)col;
                    if (key < dist[col]) { dist[col] = key; path[col] = (unsigned char)i; }
                    if (key < local) local = key;
                }
            }
            // rescan owned columns (stale reads are safe: relaxer covers new keys)
            for (int j = tid; j < NQ; j += 128) {
                unsigned long long dv = dist[j];
                if (dv < local) local = dv;
            }
            if (local != KMAX) atomicMin(&s_best, local);
            __syncthreads();

            if (tid == 0) {
                unsigned long long best = s_best;
                s_best = KMAX;
                if (best == KMAX) {           // infeasible guard (never hit)
                    s_done = 1; s_sink = -1; s_fm = 0.0;
                } else {
                    int j = (int)(best & 1023ull);
                    double dval = __longlong_as_double((long long)(best & ~1023ull));
                    sccol[s_len] = (unsigned short)j;
                    scval[s_len] = dval;
                    s_len++;
                    scflag[j] = 1;
                    dist[j] = KMAX;
                    int r2 = row4col[j];
                    if (r2 < 0) { s_done = 1; s_sink = j; s_fm = dval; }
                    else        { s_i = r2; s_minval = dval; }
                }
            }
            __syncthreads();
            if (s_done) break;
        }

        // dual updates over the tree only (reads row4col BEFORE augment)
        int len = s_len;
        double fm = s_fm;
        for (int k = tid; k < len; k += 128) {
            int ck = sccol[k];
            double dv = scval[k];
            v[ck] -= fm - dv;
            int rr = row4col[ck];
            if (rr >= 0) u[rr] += fm - dv;
        }
        if (tid == 0) u[curRow] += fm;
        __syncthreads();

        if (tid == 0 && s_sink >= 0) {
            int j = s_sink;
            while (true) {
                int i2 = path[j];
                row4col[j] = (short)i2;
                int old = col4row[i2];
                col4row[i2] = (short)j;
                if (i2 == curRow) break;
                j = old;
            }
        }
        for (int k = tid; k < len; k += 128) scflag[sccol[k]] = 0;
        __syncthreads();
    }

    if (tid < NT) g_match[b * NT + tid] = col4row[tid];
}

static const int HSM_SIZE =
    NQ * 8 + NQ * 8 + NQ * 8 + NT * 8 +        // v, dist, scval, u
    NT * CAP * 4 + NT * CAP * 2 +              // ccost, ccol
    NQ * 2 + NT * 2 + NQ * 2 + NT * 2 +        // row4col, col4row, sccol, cnt_s
    NQ + NQ + 16;                              // path, scflag, pad

// ---------------------------------------------------------------------------
// Kernel 4: per-image loss (bbox L1 + GIoU + weighted CE over 900 queries)
// ---------------------------------------------------------------------------
__device__ __forceinline__ double block_reduce(double val, double* red, int tid) {
    red[tid] = val;
    __syncthreads();
    for (int s = 128; s > 0; s >>= 1) {
        if (tid < s) red[tid] += red[tid + s];
        __syncthreads();
    }
    double r = red[0];
    __syncthreads();
    return r;
}

__global__ void __launch_bounds__(256) loss_kernel(const float* __restrict__ pc,
                                                   const float* __restrict__ pb,
                                                   const int*   __restrict__ tl,
                                                   const float* __restrict__ tb) {
    int b = blockIdx.x, tid = threadIdx.x;
    __shared__ int cls[NQ];
    __shared__ double red[256];

    for (int q = tid; q < NQ; q += 256) cls[q] = NC - 1;
    __syncthreads();

    double l1sum = 0.0, gsum = 0.0;
    if (tid < NT) {
        int t = tid;
        int q = g_match[b * NT + t];
        int lab = tl[b * NT + t];
        cls[q] = lab;

        float4 p4 = reinterpret_cast<const float4*>(pb)[b * NQ + q];
        float4 t4 = reinterpret_cast<const float4*>(tb)[b * NT + t];
        l1sum = (double)(fabsf(p4.x - t4.x) + fabsf(p4.y - t4.y) +
                         fabsf(p4.z - t4.z) + fabsf(p4.w - t4.w));

        float px0 = p4.x - 0.5f * p4.z, py0 = p4.y - 0.5f * p4.w;
        float px1 = p4.x + 0.5f * p4.z, py1 = p4.y + 0.5f * p4.w;
        float tx0 = t4.x - 0.5f * t4.z, ty0 = t4.y - 0.5f * t4.w;
        float tx1 = t4.x + 0.5f * t4.z, ty1 = t4.y + 0.5f * t4.w;
        float a1 = (px1 - px0) * (py1 - py0);
        float a2 = (tx1 - tx0) * (ty1 - ty0);
        float ltx = fmaxf(px0, tx0), lty = fmaxf(py0, ty0);
        float rbx = fminf(px1, tx1), rby = fminf(py1, ty1);
        float iw = fmaxf(rbx - ltx, 0.f), ih = fmaxf(rby - lty, 0.f);
        float inter = iw * ih;
        float uni = a1 + a2 - inter;
        float iou = inter / uni;
        float cx0 = fminf(px0, tx0), cy0 = fminf(py0, ty0);
        float cx1 = fmaxf(px1, tx1), cy1 = fmaxf(py1, ty1);
        float cw = fmaxf(cx1 - cx0, 0.f), ch = fmaxf(cy1 - cy0, 0.f);
        float ac = cw * ch;
        float giou = iou - (ac - uni) / ac;
        gsum = (double)(1.0f - giou);
    }
    __syncthreads();

    double wnll = 0.0, wsum = 0.0;
    for (int q = tid; q < NQ; q += 256) {
        const float* lg = pc + ((size_t)b * NQ + q) * NC;
        float lgl[NC];
        float m = -FLT_MAX;
        #pragma unroll
        for (int k = 0; k < NC; k++) { lgl[k] = lg[k]; m = fmaxf(m, lgl[k]); }
        float s = 0.f;
        #pragma unroll
        for (int k = 0; k < NC; k++) s += expf(lgl[k] - m);
        float lse = logf(s) + m;
        int c = cls[q];
        float nll = lse - lgl[c];
        float w = (c == NC - 1) ? 0.05f : 1.0f;
        wnll += (double)(w * nll);
        wsum += (double)w;
    }

    double L1 = block_reduce(l1sum, red, tid);
    double G  = block_reduce(gsum, red, tid);
    double WN = block_reduce(wnll, red, tid);
    double WS = block_reduce(wsum, red, tid);

    if (tid == 0) {
        double l1_mean = L1 / (double)(NT * 4);
        double bbox = 5.0 * l1_mean + 2.0 * (G / (double)NT);
        g_partial[b] = WN / WS + bbox;
    }
}

__global__ void finalize_kernel(float* out) {
    __shared__ double red[64];
    int tid = threadIdx.x;
    red[tid] = g_partial[tid];
    __syncthreads();
    for (int s = 32; s > 0; s >>= 1) {
        if (tid < s) red[tid] += red[tid + s];
        __syncthreads();
    }
    if (tid == 0) out[0] = (float)(red[0] / (double)(BATCH * NT));
}

// ---------------------------------------------------------------------------
extern "C" void kernel_launch(void* const* d_in, const int* in_sizes, int n_in,
                              void* d_out, int out_size) {
    const float* pc = (const float*)d_in[0];  // [64,900,14]
    const float* pb = (const float*)d_in[1];  // [64,900,4]
    const int*   tl = (const int*)d_in[2];    // [64,128]
    const float* tb = (const float*)d_in[3];  // [64,128,4]

    cudaFuncSetAttribute(hungarian_kernel,
                         cudaFuncAttributeMaxDynamicSharedMemorySize, HSM_SIZE);

    cost_kernel<<<BATCH, 256>>>(pc, pb, tl, tb);
    select_kernel<<<BATCH * NT, 128>>>();
    hungarian_kernel<<<BATCH, 128, HSM_SIZE>>>();
    loss_kernel<<<BATCH, 256>>>(pc, pb, tl, tb);
    finalize_kernel<<<1, 64>>>((float*)d_out);
}